// round 15
// baseline (speedup 1.0000x reference)
#include <cuda_runtime.h>
#include <cuda_fp16.h>
#include <cstdint>

// ---------------------------------------------------------------------------
// GlobalGNN layer-1-only pipeline (4 kernels):
//   s2  : xW = x@gcn_W^T (fp16 MMA m16n8k16, fp32 accum, fp16 out)
//   main: hist+scan (last-block-done fusion) -> scatter(x2)
//   join: fused gather (gather_gcn || grid barrier || sage2)  -> sage_out
// State self-restoring across graph replays.
// ---------------------------------------------------------------------------

#define H 128
#define MAXN0 131072
#define MAXN2 16384
#define MAXE  1048576
#define GROWS 64
#define HSTR 136
#define HS2  264

__device__ __align__(16) __half g_xWh  [(size_t)MAXN0 * H];
__device__ __align__(16) __half g_aggh [(size_t)MAXN2 * H];
__device__ __align__(16) __half g_g1h  [(size_t)MAXN2 * H];
__device__ __align__(16) __half g_meanh[(size_t)MAXN2 * H];
__device__ __align__(16) __half g_p1h  [(size_t)MAXN2 * H];
__device__ __align__(16) int    g_hd   [2 * MAXN2];
__device__ __align__(16) int    g_off  [MAXN2 + 4];
__device__ __align__(16) float2 g_epk  [MAXE];
__device__ __align__(16) float  g_wst  [MAXE];
__device__ unsigned g_done = 0;
__device__ unsigned g_barCnt = 0;
__device__ unsigned g_barGen = 0;

__device__ __forceinline__ void grid_barrier() {
    __syncthreads();
    if (threadIdx.x == 0) {
        unsigned gen = atomicAdd(&g_barGen, 0u);
        __threadfence();
        unsigned old = atomicAdd(&g_barCnt, 1u);
        if (old == gridDim.x - 1u) {
            g_barCnt = 0;
            __threadfence();
            atomicAdd(&g_barGen, 1u);
        } else {
            while (atomicAdd(&g_barGen, 0u) == gen) { }
        }
        __threadfence();
    }
    __syncthreads();
}

__device__ __forceinline__ int clamp_n1(const int* p, int N0) {
    int v = *p;
    if (v <= 0 || v > N0) v = N0;
    return v;
}

__device__ __forceinline__ float4 h4_to_f4(uint2 raw) {
    __half2 h0 = *reinterpret_cast<__half2*>(&raw.x);
    __half2 h1 = *reinterpret_cast<__half2*>(&raw.y);
    float2 f0 = __half22float2(h0);
    float2 f1 = __half22float2(h1);
    return make_float4(f0.x, f0.y, f1.x, f1.y);
}

__device__ __forceinline__ uint2 f4_to_h4(float4 v) {
    __half2 h0 = __floats2half2_rn(v.x, v.y);
    __half2 h1 = __floats2half2_rn(v.z, v.w);
    uint2 r;
    r.x = *reinterpret_cast<uint32_t*>(&h0);
    r.y = *reinterpret_cast<uint32_t*>(&h1);
    return r;
}

#define MMA_F16(d, a0, a1, a2, a3, b0, b1)                                    \
    asm volatile(                                                             \
        "mma.sync.aligned.m16n8k16.row.col.f32.f16.f16.f32 "                  \
        "{%0,%1,%2,%3},{%4,%5,%6,%7},{%8,%9},{%0,%1,%2,%3};"                  \
        : "+f"(d[0]), "+f"(d[1]), "+f"(d[2]), "+f"(d[3])                      \
        : "r"(a0), "r"(a1), "r"(a2), "r"(a3), "r"(b0), "r"(b1))

// ---- K1: histogram (2 edges/thread) + inline scan by last-done block -----------
__global__ void __launch_bounds__(1024) k_hist_scan(
    const float* __restrict__ attr, const int* __restrict__ eid,
    const int* __restrict__ tgt, int E, int n2) {
    __shared__ int wsum[32];
    __shared__ int sh_last;
    int tid = threadIdx.x;

    int base = (blockIdx.x * 1024 + tid) * 2;
    if (base < E) {
        if (base + 2 <= E) {
            int2 t2  = *(const int2*)&tgt[base];
            int2 id2 = *(const int2*)&eid[base];
            float w0 = __ldg(&attr[id2.x]);
            float w1 = __ldg(&attr[id2.y]);
            *(float2*)&g_wst[base] = make_float2(w0, w1);
            if (t2.x < n2) { atomicAdd(&g_hd[t2.x], 1); atomicAdd((float*)&g_hd[MAXN2 + t2.x], w0); }
            if (t2.y < n2) { atomicAdd(&g_hd[t2.y], 1); atomicAdd((float*)&g_hd[MAXN2 + t2.y], w1); }
        } else {
            int t = __ldg(&tgt[base]);
            float w = __ldg(&attr[__ldg(&eid[base])]);
            g_wst[base] = w;
            if (t < n2) {
                atomicAdd(&g_hd[t], 1);
                atomicAdd((float*)&g_hd[MAXN2 + t], w);
            }
        }
    }

    // last-done detection
    __syncthreads();
    __threadfence();
    if (tid == 0) {
        unsigned ticket = atomicAdd(&g_done, 1u);
        sh_last = (ticket == gridDim.x - 1u) ? 1 : 0;
        if (sh_last) g_done = 0;  // reset for next replay
    }
    __syncthreads();
    if (!sh_last) return;

    // ---- inline exclusive scan over counts (this block only, 1024 threads) ----
    int lane = tid & 31, wid = tid >> 5;
    int sbase = tid * 16;
    int vals[16], cnts[16];
    int local = 0;
#pragma unroll
    for (int i4 = 0; i4 < 4; ++i4) {
        int4 q = __ldcg((const int4*)&g_hd[sbase + i4 * 4]);   // L2-coherent
        int cc[4] = {q.x, q.y, q.z, q.w};
#pragma unroll
        for (int j = 0; j < 4; ++j) {
            int idx = sbase + i4 * 4 + j;
            int c = (idx < n2) ? cc[j] : 0;
            vals[i4 * 4 + j] = local;
            cnts[i4 * 4 + j] = c;
            local += c;
        }
    }
    int inc = local;
#pragma unroll
    for (int off = 1; off < 32; off <<= 1) {
        int nb = __shfl_up_sync(0xffffffffu, inc, off);
        if (lane >= off) inc += nb;
    }
    if (lane == 31) wsum[wid] = inc;
    __syncthreads();
    if (wid == 0) {
        int s = wsum[lane];
#pragma unroll
        for (int off = 1; off < 32; off <<= 1) {
            int nb = __shfl_up_sync(0xffffffffu, s, off);
            if (lane >= off) s += nb;
        }
        wsum[lane] = s;
    }
    __syncthreads();
    int excl = ((wid > 0) ? wsum[wid - 1] : 0) + inc - local;
#pragma unroll
    for (int i4 = 0; i4 < 4; ++i4) {
        int idx = sbase + i4 * 4;
        int4 q = make_int4(excl + vals[i4 * 4],     excl + vals[i4 * 4 + 1],
                           excl + vals[i4 * 4 + 2], excl + vals[i4 * 4 + 3]);
        if (idx + 3 < n2) {
            *(int4*)&g_off[idx] = q;
            int4 e = make_int4(q.x + cnts[i4 * 4],     q.y + cnts[i4 * 4 + 1],
                               q.z + cnts[i4 * 4 + 2], q.w + cnts[i4 * 4 + 3]);
            *(int4*)&g_hd[idx] = e;
        } else {
#pragma unroll
            for (int j = 0; j < 4; ++j) {
                if (idx + j < n2) {
                    g_off[idx + j] = (&q.x)[j];
                    g_hd[idx + j] = (&q.x)[j] + cnts[i4 * 4 + j];
                }
            }
        }
    }
    if (tid == 0) g_off[n2] = wsum[31];
}

// ---- K2: scatter (countdown on end positions), 2 edges/thread ------------------
__global__ void k_scatter(const int* __restrict__ src, const int* __restrict__ tgt,
                          int E, int n2) {
    int base = (blockIdx.x * blockDim.x + threadIdx.x) * 2;
    if (base >= E) return;
    int t[2], s[2];
    float w[2];
    if (base + 2 <= E) {
        int2 t2 = *(const int2*)&tgt[base];
        int2 s2 = *(const int2*)&src[base];
        float2 w2 = *(const float2*)&g_wst[base];
        t[0] = t2.x; t[1] = t2.y;
        s[0] = s2.x; s[1] = s2.y;
        w[0] = w2.x; w[1] = w2.y;
    } else {
        t[0] = __ldg(&tgt[base]); t[1] = n2;
        s[0] = __ldg(&src[base]); s[1] = 0;
        w[0] = __ldg(&g_wst[base]); w[1] = 0.f;
    }
    int pos[2];
#pragma unroll
    for (int j = 0; j < 2; ++j)
        pos[j] = (t[j] < n2) ? (atomicAdd(&g_hd[t[j]], -1) - 1) : -1;
#pragma unroll
    for (int j = 0; j < 2; ++j)
        if (pos[j] >= 0)
            g_epk[pos[j]] = make_float2(__int_as_float(s[j]), w[j]);
}

// ---- K3: xW = x @ W^T via fp16 MMA (m16n8k16, fp32 accum), rows < n1 -----------
__global__ void __launch_bounds__(256) k_gemm_tc(
    const float* __restrict__ x, const float* __restrict__ W,
    const int* __restrict__ n1p, int N0) {
    extern __shared__ __half hsm[];
    __half* xs = hsm;
    __half* ws = hsm + 128 * HSTR;

    int n1 = clamp_n1(n1p, N0);
    int row0 = blockIdx.x * 128;
    if (row0 >= n1) return;

    int tid = threadIdx.x, lane = tid & 31, warp = tid >> 5;
    int wm = warp >> 1, wn = warp & 1;
    int lq = lane >> 2, lr = lane & 3;

#pragma unroll
    for (int it = 0; it < 16; ++it) {
        int f4 = it * 256 + tid;
        int r = f4 >> 5, k4 = f4 & 31;
        int row = row0 + r;
        float4 v = make_float4(0.f, 0.f, 0.f, 0.f);
        if (row < N0) v = *(const float4*)&x[(size_t)row * H + k4 * 4];
        *(uint2*)&xs[r * HSTR + k4 * 4] = f4_to_h4(v);
        float4 wv = *(const float4*)&W[(size_t)r * H + k4 * 4];
        *(uint2*)&ws[r * HSTR + k4 * 4] = f4_to_h4(wv);
    }
    __syncthreads();

    float acc[2][8][4];
#pragma unroll
    for (int mi = 0; mi < 2; ++mi)
#pragma unroll
        for (int ni = 0; ni < 8; ++ni)
#pragma unroll
            for (int j = 0; j < 4; ++j) acc[mi][ni][j] = 0.f;

#pragma unroll
    for (int ks = 0; ks < 8; ++ks) {
        int kb = ks * 16;
        uint32_t a[2][4];
#pragma unroll
        for (int mi = 0; mi < 2; ++mi) {
            int r0 = wm * 32 + mi * 16 + lq;
            a[mi][0] = *(const uint32_t*)&xs[r0 * HSTR + kb + lr * 2];
            a[mi][1] = *(const uint32_t*)&xs[(r0 + 8) * HSTR + kb + lr * 2];
            a[mi][2] = *(const uint32_t*)&xs[r0 * HSTR + kb + 8 + lr * 2];
            a[mi][3] = *(const uint32_t*)&xs[(r0 + 8) * HSTR + kb + 8 + lr * 2];
        }
#pragma unroll
        for (int ni = 0; ni < 8; ++ni) {
            int n = wn * 64 + ni * 8 + lq;
            uint32_t b0 = *(const uint32_t*)&ws[n * HSTR + kb + lr * 2];
            uint32_t b1 = *(const uint32_t*)&ws[n * HSTR + kb + 8 + lr * 2];
#pragma unroll
            for (int mi = 0; mi < 2; ++mi)
                MMA_F16(acc[mi][ni], a[mi][0], a[mi][1], a[mi][2], a[mi][3], b0, b1);
        }
    }

#pragma unroll
    for (int mi = 0; mi < 2; ++mi) {
        int r0 = row0 + wm * 32 + mi * 16 + lq;
#pragma unroll
        for (int ni = 0; ni < 8; ++ni) {
            int col = wn * 64 + ni * 8 + lr * 2;
            if (r0 < n1) {
                __half2 h = __floats2half2_rn(acc[mi][ni][0], acc[mi][ni][1]);
                *(__half2*)&g_xWh[(size_t)r0 * H + col] = h;
            }
            if (r0 + 8 < n1) {
                __half2 h = __floats2half2_rn(acc[mi][ni][2], acc[mi][ni][3]);
                *(__half2*)&g_xWh[(size_t)(r0 + 8) * H + col] = h;
            }
        }
    }
}

// ---- K4: persistent fused gather: gcn+p1 || barrier || sage2 -------------------
__global__ void __launch_bounds__(256) k_fused_gather(const float* __restrict__ b, int n2) {
    int lane = threadIdx.x & 31;
    int warp = threadIdx.x >> 5;
    int c = lane * 4;
    int tstride = gridDim.x * 8;
    int t0 = blockIdx.x * 8 + warp;

    // phase 1: GCN gather + p1
    for (int t = t0; t < n2; t += tstride) {
        int base = __ldg(&g_off[t]);
        int end  = __ldg(&g_off[t + 1]);
        float4 ag0 = make_float4(0.f, 0.f, 0.f, 0.f), ag1 = ag0;
        float4 ap0 = ag0, ap1 = ag0;

        for (int i0 = base; i0 < end; i0 += 32) {
            int idx = i0 + lane;
            int s = 0;
            uint32_t pk = 0;
            if (idx < end) {
                float2 p = __ldg(&g_epk[idx]);
                s = __float_as_int(p.x);
                float w = p.y;
                float ds = 1.f, d2 = 1.f;
                if (s < n2) {
                    float dg = __int_as_float(__ldg(&g_hd[MAXN2 + s]));
                    d2 = 1.f / (1.f + dg);
                    ds = rsqrtf(1.f + dg);
                }
                __half2 ph = __floats2half2_rn(ds * w, d2);
                pk = *reinterpret_cast<uint32_t*>(&ph);
            }
            int cnt = min(32, end - i0);
            int j = 0;
            for (; j + 8 <= cnt; j += 8) {
                int ss[8]; uint32_t pp[8];
#pragma unroll
                for (int q = 0; q < 8; ++q) {
                    ss[q] = __shfl_sync(0xffffffffu, s, j + q);
                    pp[q] = __shfl_sync(0xffffffffu, pk, j + q);
                }
                uint2 raw[8];
#pragma unroll
                for (int q = 0; q < 8; ++q)
                    raw[q] = *(const uint2*)&g_xWh[(size_t)ss[q] * H + c];
#pragma unroll
                for (int q = 0; q < 8; ++q) {
                    float2 wu = __half22float2(*reinterpret_cast<__half2*>(&pp[q]));
                    float4 v = h4_to_f4(raw[q]);
                    float4& ag = (q & 1) ? ag1 : ag0;
                    float4& ap = (q & 1) ? ap1 : ap0;
                    ag.x += wu.x * v.x; ag.y += wu.x * v.y; ag.z += wu.x * v.z; ag.w += wu.x * v.w;
                    ap.x += wu.y * v.x; ap.y += wu.y * v.y; ap.z += wu.y * v.z; ap.w += wu.y * v.w;
                }
            }
            for (; j < cnt; ++j) {
                int s0 = __shfl_sync(0xffffffffu, s, j);
                uint32_t p0 = __shfl_sync(0xffffffffu, pk, j);
                float2 wu = __half22float2(*reinterpret_cast<__half2*>(&p0));
                float4 v = h4_to_f4(*(const uint2*)&g_xWh[(size_t)s0 * H + c]);
                ag0.x += wu.x * v.x; ag0.y += wu.x * v.y; ag0.z += wu.x * v.z; ag0.w += wu.x * v.w;
                ap0.x += wu.y * v.x; ap0.y += wu.y * v.y; ap0.z += wu.y * v.z; ap0.w += wu.y * v.w;
            }
        }

        float degt = __int_as_float(g_hd[MAXN2 + t]);
        float dt  = rsqrtf(1.f + degt);
        float d2t = 1.f / (1.f + degt);
        float4 agg;
        agg.x = (ag0.x + ag1.x) * dt;
        agg.y = (ag0.y + ag1.y) * dt;
        agg.z = (ag0.z + ag1.z) * dt;
        agg.w = (ag0.w + ag1.w) * dt;
        float4 p1 = make_float4(ap0.x + ap1.x, ap0.y + ap1.y, ap0.z + ap1.z, ap0.w + ap1.w);
        float4 xw = h4_to_f4(*(const uint2*)&g_xWh[(size_t)t * H + c]);
        float4 bb = *(const float4*)&b[c];
        float4 g1;
        g1.x = agg.x + xw.x * d2t + bb.x;
        g1.y = agg.y + xw.y * d2t + bb.y;
        g1.z = agg.z + xw.z * d2t + bb.z;
        g1.w = agg.w + xw.w * d2t + bb.w;
        *(uint2*)&g_g1h[(size_t)t * H + c] = f4_to_h4(g1);
        *(uint2*)&g_aggh[(size_t)t * H + c] = f4_to_h4(agg);
        *(uint2*)&g_p1h[(size_t)t * H + c] = f4_to_h4(p1);
    }

    grid_barrier();

    // phase 2: SAGE p2 gather + mean; restore g_hd to zero
    for (int t = t0; t < n2; t += tstride) {
        int base = __ldg(&g_off[t]);
        int end  = __ldg(&g_off[t + 1]);
        int cnt = end - base;
        if (lane == 0) { g_hd[t] = 0; g_hd[MAXN2 + t] = 0; }

        float4 a0 = make_float4(0.f, 0.f, 0.f, 0.f), a1 = a0;
        for (int i0 = base; i0 < end; i0 += 32) {
            int idx = i0 + lane;
            int s = n2;
            if (idx < end) s = __float_as_int(__ldg(&g_epk[idx]).x);
            int cl = min(32, end - i0);
            int j = 0;
            for (; j + 8 <= cl; j += 8) {
                int ss[8];
#pragma unroll
                for (int q = 0; q < 8; ++q)
                    ss[q] = __shfl_sync(0xffffffffu, s, j + q);
#pragma unroll
                for (int q = 0; q < 8; ++q) {
                    if (ss[q] < n2) {
                        float4 v = h4_to_f4(*(const uint2*)&g_aggh[(size_t)ss[q] * H + c]);
                        float4& a = (q & 1) ? a1 : a0;
                        a.x += v.x; a.y += v.y; a.z += v.z; a.w += v.w;
                    }
                }
            }
            for (; j < cl; ++j) {
                int s0 = __shfl_sync(0xffffffffu, s, j);
                if (s0 < n2) {
                    float4 v = h4_to_f4(*(const uint2*)&g_aggh[(size_t)s0 * H + c]);
                    a0.x += v.x; a0.y += v.y; a0.z += v.z; a0.w += v.w;
                }
            }
        }

        float4 o = make_float4(0.f, 0.f, 0.f, 0.f);
        if (cnt > 0) {
            float sc = 1.f / (float)cnt;
            float4 p1 = h4_to_f4(*(const uint2*)&g_p1h[(size_t)t * H + c]);
            float4 bb = *(const float4*)&b[c];
            o.x = (p1.x + a0.x + a1.x) * sc + bb.x;
            o.y = (p1.y + a0.y + a1.y) * sc + bb.y;
            o.z = (p1.z + a0.z + a1.z) * sc + bb.z;
            o.w = (p1.w + a0.w + a1.w) * sc + bb.w;
        }
        *(uint2*)&g_meanh[(size_t)t * H + c] = f4_to_h4(o);
    }
}

// ---- K5: out = l2norm( [mean|g1] @ [Wl|Wr]^T + bl ), K=256 fp16 MMA ------------
__global__ void __launch_bounds__(256) k_sage_out(
    const float* __restrict__ Wl, const float* __restrict__ bl,
    const float* __restrict__ Wr, int n2, float* __restrict__ out) {
    extern __shared__ __half hsm[];
    __half* As = hsm;
    __half* Bs = hsm + 64 * HS2;
    float* psum = (float*)(hsm + 192 * HS2);
    float* scl  = psum + GROWS * 8;

    int row0 = blockIdx.x * GROWS;
    int tid = threadIdx.x, lane = tid & 31, warp = tid >> 5;
    int wm = warp >> 1, wn = warp & 1;
    int lq = lane >> 2, lr = lane & 3;

#pragma unroll
    for (int it = 0; it < 16; ++it) {
        int ch = it * 256 + tid;
        int r = ch >> 6, q = ch & 63;
        int row = row0 + r;
        uint2 v = make_uint2(0u, 0u);
        if (row < n2) {
            if (q < 32) v = *(const uint2*)&g_meanh[(size_t)row * H + q * 4];
            else        v = *(const uint2*)&g_g1h[(size_t)row * H + (q - 32) * 4];
        }
        int k = (q < 32) ? q * 4 : 128 + (q - 32) * 4;
        *(uint2*)&As[r * HS2 + k] = v;
    }
#pragma unroll
    for (int it = 0; it < 32; ++it) {
        int ch = it * 256 + tid;
        int j = ch >> 6, q = ch & 63;
        float4 v;
        int k;
        if (q < 32) { v = *(const float4*)&Wl[(size_t)j * H + q * 4]; k = q * 4; }
        else        { v = *(const float4*)&Wr[(size_t)j * H + (q - 32) * 4]; k = 128 + (q - 32) * 4; }
        *(uint2*)&Bs[j * HS2 + k] = f4_to_h4(v);
    }
    __syncthreads();

    float acc[8][4];
#pragma unroll
    for (int ni = 0; ni < 8; ++ni)
#pragma unroll
        for (int j = 0; j < 4; ++j) acc[ni][j] = 0.f;

#pragma unroll
    for (int ks = 0; ks < 16; ++ks) {
        int kb = ks * 16;
        int r0 = wm * 16 + lq;
        uint32_t a0 = *(const uint32_t*)&As[r0 * HS2 + kb + lr * 2];
        uint32_t a1 = *(const uint32_t*)&As[(r0 + 8) * HS2 + kb + lr * 2];
        uint32_t a2 = *(const uint32_t*)&As[r0 * HS2 + kb + 8 + lr * 2];
        uint32_t a3 = *(const uint32_t*)&As[(r0 + 8) * HS2 + kb + 8 + lr * 2];
#pragma unroll
        for (int ni = 0; ni < 8; ++ni) {
            int n = wn * 64 + ni * 8 + lq;
            uint32_t b0 = *(const uint32_t*)&Bs[n * HS2 + kb + lr * 2];
            uint32_t b1 = *(const uint32_t*)&Bs[n * HS2 + kb + 8 + lr * 2];
            MMA_F16(acc[ni], a0, a1, a2, a3, b0, b1);
        }
    }

    float p0 = 0.f, p8 = 0.f;
#pragma unroll
    for (int ni = 0; ni < 8; ++ni) {
        int col = wn * 64 + ni * 8 + lr * 2;
        float2 bb = *(const float2*)&bl[col];
        acc[ni][0] += bb.x; acc[ni][1] += bb.y;
        acc[ni][2] += bb.x; acc[ni][3] += bb.y;
        p0 += acc[ni][0] * acc[ni][0] + acc[ni][1] * acc[ni][1];
        p8 += acc[ni][2] * acc[ni][2] + acc[ni][3] * acc[ni][3];
    }
    int rl = wm * 16 + lq;
    psum[rl * 8 + wn * 4 + lr] = p0;
    psum[(rl + 8) * 8 + wn * 4 + lr] = p8;
    __syncthreads();
    if (tid < GROWS) {
        float ssum = 0.f;
#pragma unroll
        for (int c8 = 0; c8 < 8; ++c8) ssum += psum[tid * 8 + c8];
        scl[tid] = 1.f / fmaxf(sqrtf(ssum), 1e-12f);
    }
    __syncthreads();

    float s0 = scl[rl], s8 = scl[rl + 8];
    int row_a = row0 + rl, row_b = row0 + rl + 8;
#pragma unroll
    for (int ni = 0; ni < 8; ++ni) {
        int col = wn * 64 + ni * 8 + lr * 2;
        if (row_a < n2)
            *(float2*)&out[(size_t)row_a * H + col] =
                make_float2(acc[ni][0] * s0, acc[ni][1] * s0);
        if (row_b < n2)
            *(float2*)&out[(size_t)row_b * H + col] =
                make_float2(acc[ni][2] * s8, acc[ni][3] * s8);
    }
}

// ---------------------------------------------------------------------------
extern "C" void kernel_launch(void* const* d_in, const int* in_sizes, int n_in,
                              void* d_out, int out_size) {
    const float* x     = (const float*)d_in[0];
    const float* attr  = (const float*)d_in[1];
    const int*   e_id1 = (const int*)d_in[3];
    const int*   src1  = (const int*)d_in[6];
    const int*   tgt1  = (const int*)d_in[7];
    const int*   n1p   = (const int*)d_in[8];
    const float* gcn_W = (const float*)d_in[10];
    const float* gcn_b = (const float*)d_in[11];
    const float* Wl1   = (const float*)d_in[15];
    const float* bl1   = (const float*)d_in[16];
    const float* Wr1   = (const float*)d_in[17];
    float* out = (float*)d_out;

    int N0 = in_sizes[0] / H;  if (N0 > MAXN0) N0 = MAXN0;
    int E1 = in_sizes[3];      if (E1 > MAXE)  E1 = MAXE;
    int n2 = out_size / H;     if (n2 > MAXN2) n2 = MAXN2;

    constexpr int SMEM_GEMM = 2 * 128 * HSTR * 2;
    constexpr int SMEM_SOUT = 192 * HS2 * 2 + GROWS * 8 * 4 + GROWS * 4;
    cudaFuncSetAttribute(k_gemm_tc, cudaFuncAttributeMaxDynamicSharedMemorySize, SMEM_GEMM);
    cudaFuncSetAttribute(k_sage_out, cudaFuncAttributeMaxDynamicSharedMemorySize, SMEM_SOUT);

    // conservative co-resident grid for the persistent fused gather
    int nsm = 0, maxb = 0;
    cudaDeviceGetAttribute(&nsm, cudaDevAttrMultiProcessorCount, 0);
    cudaOccupancyMaxActiveBlocksPerMultiprocessor(&maxb, k_fused_gather, 256, 0);
    if (nsm <= 0) nsm = 1;
    if (maxb <= 0) maxb = 1;
    int bpsm = maxb < 4 ? maxb : 4;
    int gatherGrid = nsm * bpsm;

    cudaStream_t s2;
    cudaStreamCreateWithFlags(&s2, cudaStreamNonBlocking);
    cudaEvent_t evFork, evGemm;
    cudaEventCreateWithFlags(&evFork, cudaEventDisableTiming);
    cudaEventCreateWithFlags(&evGemm, cudaEventDisableTiming);

    cudaEventRecord(evFork, 0);
    cudaStreamWaitEvent(s2, evFork, 0);
    k_gemm_tc<<<(N0 + 127) / 128, 256, SMEM_GEMM, s2>>>(x, gcn_W, n1p, N0);
    cudaEventRecord(evGemm, s2);

    k_hist_scan<<<(E1 + 2047) / 2048, 1024>>>(attr, e_id1, tgt1, E1, n2);
    k_scatter<<<(E1 + 511) / 512, 256>>>(src1, tgt1, E1, n2);

    cudaStreamWaitEvent(0, evGemm, 0);

    k_fused_gather<<<gatherGrid, 256>>>(gcn_b, n2);
    k_sage_out<<<(n2 + GROWS - 1) / GROWS, 256, SMEM_SOUT>>>(Wl1, bl1, Wr1, n2, out);
}

// round 16
// speedup vs baseline: 1.0321x; 1.0321x over previous
#include <cuda_runtime.h>
#include <cuda_fp16.h>
#include <cstdint>

// ---------------------------------------------------------------------------
// GlobalGNN layer-1-only pipeline (5 kernels):
//   s2  : xW = x@gcn_W^T (fp16 MMA m16n8k16, fp32 accum, fp16 out)
//   main: hist+scan (last-block-done fusion) -> scatter(x2)
//   join: gather_gcn -> sage2 -> sage_out (K=256 fp16 MMA + l2norm)
// State self-restoring across graph replays.
// ---------------------------------------------------------------------------

#define H 128
#define MAXN0 131072
#define MAXN2 16384
#define MAXE  1048576
#define GROWS 64
#define HSTR 136
#define HS2  264

__device__ __align__(16) __half g_xWh  [(size_t)MAXN0 * H];
__device__ __align__(16) __half g_aggh [(size_t)MAXN2 * H];
__device__ __align__(16) __half g_g1h  [(size_t)MAXN2 * H];
__device__ __align__(16) __half g_meanh[(size_t)MAXN2 * H];
__device__ __align__(16) __half g_p1h  [(size_t)MAXN2 * H];
__device__ __align__(16) int    g_hd   [2 * MAXN2];
__device__ __align__(16) int    g_off  [MAXN2 + 4];
__device__ __align__(16) float2 g_epk  [MAXE];
__device__ __align__(16) float  g_wst  [MAXE];
__device__ unsigned g_done = 0;

__device__ __forceinline__ int clamp_n1(const int* p, int N0) {
    int v = *p;
    if (v <= 0 || v > N0) v = N0;
    return v;
}

__device__ __forceinline__ float4 h4_to_f4(uint2 raw) {
    __half2 h0 = *reinterpret_cast<__half2*>(&raw.x);
    __half2 h1 = *reinterpret_cast<__half2*>(&raw.y);
    float2 f0 = __half22float2(h0);
    float2 f1 = __half22float2(h1);
    return make_float4(f0.x, f0.y, f1.x, f1.y);
}

__device__ __forceinline__ uint2 f4_to_h4(float4 v) {
    __half2 h0 = __floats2half2_rn(v.x, v.y);
    __half2 h1 = __floats2half2_rn(v.z, v.w);
    uint2 r;
    r.x = *reinterpret_cast<uint32_t*>(&h0);
    r.y = *reinterpret_cast<uint32_t*>(&h1);
    return r;
}

#define MMA_F16(d, a0, a1, a2, a3, b0, b1)                                    \
    asm volatile(                                                             \
        "mma.sync.aligned.m16n8k16.row.col.f32.f16.f16.f32 "                  \
        "{%0,%1,%2,%3},{%4,%5,%6,%7},{%8,%9},{%0,%1,%2,%3};"                  \
        : "+f"(d[0]), "+f"(d[1]), "+f"(d[2]), "+f"(d[3])                      \
        : "r"(a0), "r"(a1), "r"(a2), "r"(a3), "r"(b0), "r"(b1))

// ---- K1: histogram (2 edges/thread) + inline scan by last-done block -----------
__global__ void __launch_bounds__(1024) k_hist_scan(
    const float* __restrict__ attr, const int* __restrict__ eid,
    const int* __restrict__ tgt, int E, int n2) {
    __shared__ int wsum[32];
    __shared__ int sh_last;
    int tid = threadIdx.x;

    int base = (blockIdx.x * 1024 + tid) * 2;
    if (base < E) {
        if (base + 2 <= E) {
            int2 t2  = *(const int2*)&tgt[base];
            int2 id2 = *(const int2*)&eid[base];
            float w0 = __ldg(&attr[id2.x]);
            float w1 = __ldg(&attr[id2.y]);
            *(float2*)&g_wst[base] = make_float2(w0, w1);
            if (t2.x < n2) { atomicAdd(&g_hd[t2.x], 1); atomicAdd((float*)&g_hd[MAXN2 + t2.x], w0); }
            if (t2.y < n2) { atomicAdd(&g_hd[t2.y], 1); atomicAdd((float*)&g_hd[MAXN2 + t2.y], w1); }
        } else {
            int t = __ldg(&tgt[base]);
            float w = __ldg(&attr[__ldg(&eid[base])]);
            g_wst[base] = w;
            if (t < n2) {
                atomicAdd(&g_hd[t], 1);
                atomicAdd((float*)&g_hd[MAXN2 + t], w);
            }
        }
    }

    __syncthreads();
    __threadfence();
    if (tid == 0) {
        unsigned ticket = atomicAdd(&g_done, 1u);
        sh_last = (ticket == gridDim.x - 1u) ? 1 : 0;
        if (sh_last) g_done = 0;
    }
    __syncthreads();
    if (!sh_last) return;

    // inline exclusive scan over counts (1024 threads, 16 items each)
    int lane = tid & 31, wid = tid >> 5;
    int sbase = tid * 16;
    int vals[16], cnts[16];
    int local = 0;
#pragma unroll
    for (int i4 = 0; i4 < 4; ++i4) {
        int4 q = __ldcg((const int4*)&g_hd[sbase + i4 * 4]);
        int cc[4] = {q.x, q.y, q.z, q.w};
#pragma unroll
        for (int j = 0; j < 4; ++j) {
            int idx = sbase + i4 * 4 + j;
            int cv = (idx < n2) ? cc[j] : 0;
            vals[i4 * 4 + j] = local;
            cnts[i4 * 4 + j] = cv;
            local += cv;
        }
    }
    int inc = local;
#pragma unroll
    for (int off = 1; off < 32; off <<= 1) {
        int nb = __shfl_up_sync(0xffffffffu, inc, off);
        if (lane >= off) inc += nb;
    }
    if (lane == 31) wsum[wid] = inc;
    __syncthreads();
    if (wid == 0) {
        int s = wsum[lane];
#pragma unroll
        for (int off = 1; off < 32; off <<= 1) {
            int nb = __shfl_up_sync(0xffffffffu, s, off);
            if (lane >= off) s += nb;
        }
        wsum[lane] = s;
    }
    __syncthreads();
    int excl = ((wid > 0) ? wsum[wid - 1] : 0) + inc - local;
#pragma unroll
    for (int i4 = 0; i4 < 4; ++i4) {
        int idx = sbase + i4 * 4;
        int4 q = make_int4(excl + vals[i4 * 4],     excl + vals[i4 * 4 + 1],
                           excl + vals[i4 * 4 + 2], excl + vals[i4 * 4 + 3]);
        if (idx + 3 < n2) {
            *(int4*)&g_off[idx] = q;
            int4 e = make_int4(q.x + cnts[i4 * 4],     q.y + cnts[i4 * 4 + 1],
                               q.z + cnts[i4 * 4 + 2], q.w + cnts[i4 * 4 + 3]);
            *(int4*)&g_hd[idx] = e;
        } else {
#pragma unroll
            for (int j = 0; j < 4; ++j) {
                if (idx + j < n2) {
                    g_off[idx + j] = (&q.x)[j];
                    g_hd[idx + j] = (&q.x)[j] + cnts[i4 * 4 + j];
                }
            }
        }
    }
    if (tid == 0) g_off[n2] = wsum[31];
}

// ---- K2: scatter (countdown on end positions), 2 edges/thread ------------------
__global__ void k_scatter(const int* __restrict__ src, const int* __restrict__ tgt,
                          int E, int n2) {
    int base = (blockIdx.x * blockDim.x + threadIdx.x) * 2;
    if (base >= E) return;
    int t[2], s[2];
    float w[2];
    if (base + 2 <= E) {
        int2 t2 = *(const int2*)&tgt[base];
        int2 s2 = *(const int2*)&src[base];
        float2 w2 = *(const float2*)&g_wst[base];
        t[0] = t2.x; t[1] = t2.y;
        s[0] = s2.x; s[1] = s2.y;
        w[0] = w2.x; w[1] = w2.y;
    } else {
        t[0] = __ldg(&tgt[base]); t[1] = n2;
        s[0] = __ldg(&src[base]); s[1] = 0;
        w[0] = __ldg(&g_wst[base]); w[1] = 0.f;
    }
    int pos[2];
#pragma unroll
    for (int j = 0; j < 2; ++j)
        pos[j] = (t[j] < n2) ? (atomicAdd(&g_hd[t[j]], -1) - 1) : -1;
#pragma unroll
    for (int j = 0; j < 2; ++j)
        if (pos[j] >= 0)
            g_epk[pos[j]] = make_float2(__int_as_float(s[j]), w[j]);
}

// ---- K3: xW = x @ W^T via fp16 MMA (m16n8k16, fp32 accum), rows < n1 -----------
__global__ void __launch_bounds__(256) k_gemm_tc(
    const float* __restrict__ x, const float* __restrict__ W,
    const int* __restrict__ n1p, int N0) {
    extern __shared__ __half hsm[];
    __half* xs = hsm;
    __half* ws = hsm + 128 * HSTR;

    int n1 = clamp_n1(n1p, N0);
    int row0 = blockIdx.x * 128;
    if (row0 >= n1) return;

    int tid = threadIdx.x, lane = tid & 31, warp = tid >> 5;
    int wm = warp >> 1, wn = warp & 1;
    int lq = lane >> 2, lr = lane & 3;

#pragma unroll
    for (int it = 0; it < 16; ++it) {
        int f4 = it * 256 + tid;
        int r = f4 >> 5, k4 = f4 & 31;
        int row = row0 + r;
        float4 v = make_float4(0.f, 0.f, 0.f, 0.f);
        if (row < N0) v = *(const float4*)&x[(size_t)row * H + k4 * 4];
        *(uint2*)&xs[r * HSTR + k4 * 4] = f4_to_h4(v);
        float4 wv = *(const float4*)&W[(size_t)r * H + k4 * 4];
        *(uint2*)&ws[r * HSTR + k4 * 4] = f4_to_h4(wv);
    }
    __syncthreads();

    float acc[2][8][4];
#pragma unroll
    for (int mi = 0; mi < 2; ++mi)
#pragma unroll
        for (int ni = 0; ni < 8; ++ni)
#pragma unroll
            for (int j = 0; j < 4; ++j) acc[mi][ni][j] = 0.f;

#pragma unroll
    for (int ks = 0; ks < 8; ++ks) {
        int kb = ks * 16;
        uint32_t a[2][4];
#pragma unroll
        for (int mi = 0; mi < 2; ++mi) {
            int r0 = wm * 32 + mi * 16 + lq;
            a[mi][0] = *(const uint32_t*)&xs[r0 * HSTR + kb + lr * 2];
            a[mi][1] = *(const uint32_t*)&xs[(r0 + 8) * HSTR + kb + lr * 2];
            a[mi][2] = *(const uint32_t*)&xs[r0 * HSTR + kb + 8 + lr * 2];
            a[mi][3] = *(const uint32_t*)&xs[(r0 + 8) * HSTR + kb + 8 + lr * 2];
        }
#pragma unroll
        for (int ni = 0; ni < 8; ++ni) {
            int n = wn * 64 + ni * 8 + lq;
            uint32_t b0 = *(const uint32_t*)&ws[n * HSTR + kb + lr * 2];
            uint32_t b1 = *(const uint32_t*)&ws[n * HSTR + kb + 8 + lr * 2];
#pragma unroll
            for (int mi = 0; mi < 2; ++mi)
                MMA_F16(acc[mi][ni], a[mi][0], a[mi][1], a[mi][2], a[mi][3], b0, b1);
        }
    }

#pragma unroll
    for (int mi = 0; mi < 2; ++mi) {
        int r0 = row0 + wm * 32 + mi * 16 + lq;
#pragma unroll
        for (int ni = 0; ni < 8; ++ni) {
            int col = wn * 64 + ni * 8 + lr * 2;
            if (r0 < n1) {
                __half2 h = __floats2half2_rn(acc[mi][ni][0], acc[mi][ni][1]);
                *(__half2*)&g_xWh[(size_t)r0 * H + col] = h;
            }
            if (r0 + 8 < n1) {
                __half2 h = __floats2half2_rn(acc[mi][ni][2], acc[mi][ni][3]);
                *(__half2*)&g_xWh[(size_t)(r0 + 8) * H + col] = h;
            }
        }
    }
}

// ---- K4: GCN gather + SAGE partial p1 (t<n2), warp/target, unroll 8 ------------
__global__ void __launch_bounds__(256) k_gather_gcn(const float* __restrict__ b, int n2) {
    int t = blockIdx.x * 8 + (threadIdx.x >> 5);
    if (t >= n2) return;
    int lane = threadIdx.x & 31;
    int c = lane * 4;
    int base = __ldg(&g_off[t]);
    int end  = __ldg(&g_off[t + 1]);

    float4 ag0 = make_float4(0.f, 0.f, 0.f, 0.f), ag1 = ag0;
    float4 ap0 = ag0, ap1 = ag0;

    for (int i0 = base; i0 < end; i0 += 32) {
        int idx = i0 + lane;
        int s = 0;
        uint32_t pk = 0;
        if (idx < end) {
            float2 p = __ldg(&g_epk[idx]);
            s = __float_as_int(p.x);
            float w = p.y;
            float ds = 1.f, d2 = 1.f;
            if (s < n2) {
                float dg = __int_as_float(__ldg(&g_hd[MAXN2 + s]));
                d2 = 1.f / (1.f + dg);
                ds = rsqrtf(1.f + dg);
            }
            __half2 ph = __floats2half2_rn(ds * w, d2);
            pk = *reinterpret_cast<uint32_t*>(&ph);
        }
        int cnt = min(32, end - i0);
        int j = 0;
        for (; j + 8 <= cnt; j += 8) {
            int ss[8]; uint32_t pp[8];
#pragma unroll
            for (int q = 0; q < 8; ++q) {
                ss[q] = __shfl_sync(0xffffffffu, s, j + q);
                pp[q] = __shfl_sync(0xffffffffu, pk, j + q);
            }
            uint2 raw[8];
#pragma unroll
            for (int q = 0; q < 8; ++q)
                raw[q] = *(const uint2*)&g_xWh[(size_t)ss[q] * H + c];
#pragma unroll
            for (int q = 0; q < 8; ++q) {
                float2 wu = __half22float2(*reinterpret_cast<__half2*>(&pp[q]));
                float4 v = h4_to_f4(raw[q]);
                float4& ag = (q & 1) ? ag1 : ag0;
                float4& ap = (q & 1) ? ap1 : ap0;
                ag.x += wu.x * v.x; ag.y += wu.x * v.y; ag.z += wu.x * v.z; ag.w += wu.x * v.w;
                ap.x += wu.y * v.x; ap.y += wu.y * v.y; ap.z += wu.y * v.z; ap.w += wu.y * v.w;
            }
        }
        for (; j < cnt; ++j) {
            int s0 = __shfl_sync(0xffffffffu, s, j);
            uint32_t p0 = __shfl_sync(0xffffffffu, pk, j);
            float2 wu = __half22float2(*reinterpret_cast<__half2*>(&p0));
            float4 v = h4_to_f4(*(const uint2*)&g_xWh[(size_t)s0 * H + c]);
            ag0.x += wu.x * v.x; ag0.y += wu.x * v.y; ag0.z += wu.x * v.z; ag0.w += wu.x * v.w;
            ap0.x += wu.y * v.x; ap0.y += wu.y * v.y; ap0.z += wu.y * v.z; ap0.w += wu.y * v.w;
        }
    }

    float degt = __int_as_float(g_hd[MAXN2 + t]);
    float dt  = rsqrtf(1.f + degt);
    float d2t = 1.f / (1.f + degt);
    float4 agg;
    agg.x = (ag0.x + ag1.x) * dt;
    agg.y = (ag0.y + ag1.y) * dt;
    agg.z = (ag0.z + ag1.z) * dt;
    agg.w = (ag0.w + ag1.w) * dt;
    float4 p1 = make_float4(ap0.x + ap1.x, ap0.y + ap1.y, ap0.z + ap1.z, ap0.w + ap1.w);
    float4 xw = h4_to_f4(*(const uint2*)&g_xWh[(size_t)t * H + c]);
    float4 bb = *(const float4*)&b[c];
    float4 g1;
    g1.x = agg.x + xw.x * d2t + bb.x;
    g1.y = agg.y + xw.y * d2t + bb.y;
    g1.z = agg.z + xw.z * d2t + bb.z;
    g1.w = agg.w + xw.w * d2t + bb.w;
    *(uint2*)&g_g1h[(size_t)t * H + c] = f4_to_h4(g1);
    *(uint2*)&g_aggh[(size_t)t * H + c] = f4_to_h4(agg);
    *(uint2*)&g_p1h[(size_t)t * H + c] = f4_to_h4(p1);
}

// ---- K5: SAGE p2 gather + mean(fp16), unroll 8; restores g_hd[t] ---------------
__global__ void __launch_bounds__(256) k_sage2(const float* __restrict__ b, int n2) {
    int t = blockIdx.x * 8 + (threadIdx.x >> 5);
    if (t >= n2) return;
    int lane = threadIdx.x & 31;
    int c = lane * 4;
    int base = __ldg(&g_off[t]);
    int end  = __ldg(&g_off[t + 1]);
    int cnt = end - base;

    if (lane == 0) { g_hd[t] = 0; g_hd[MAXN2 + t] = 0; }

    float4 a0 = make_float4(0.f, 0.f, 0.f, 0.f), a1 = a0;

    for (int i0 = base; i0 < end; i0 += 32) {
        int idx = i0 + lane;
        int s = n2;
        if (idx < end) s = __float_as_int(__ldg(&g_epk[idx]).x);
        int cl = min(32, end - i0);
        int j = 0;
        for (; j + 8 <= cl; j += 8) {
            int ss[8];
#pragma unroll
            for (int q = 0; q < 8; ++q)
                ss[q] = __shfl_sync(0xffffffffu, s, j + q);
#pragma unroll
            for (int q = 0; q < 8; ++q) {
                if (ss[q] < n2) {
                    float4 v = h4_to_f4(*(const uint2*)&g_aggh[(size_t)ss[q] * H + c]);
                    float4& a = (q & 1) ? a1 : a0;
                    a.x += v.x; a.y += v.y; a.z += v.z; a.w += v.w;
                }
            }
        }
        for (; j < cl; ++j) {
            int s0 = __shfl_sync(0xffffffffu, s, j);
            if (s0 < n2) {
                float4 v = h4_to_f4(*(const uint2*)&g_aggh[(size_t)s0 * H + c]);
                a0.x += v.x; a0.y += v.y; a0.z += v.z; a0.w += v.w;
            }
        }
    }

    float4 o = make_float4(0.f, 0.f, 0.f, 0.f);
    if (cnt > 0) {
        float sc = 1.f / (float)cnt;
        float4 p1 = h4_to_f4(*(const uint2*)&g_p1h[(size_t)t * H + c]);
        float4 bb = *(const float4*)&b[c];
        o.x = (p1.x + a0.x + a1.x) * sc + bb.x;
        o.y = (p1.y + a0.y + a1.y) * sc + bb.y;
        o.z = (p1.z + a0.z + a1.z) * sc + bb.z;
        o.w = (p1.w + a0.w + a1.w) * sc + bb.w;
    }
    *(uint2*)&g_meanh[(size_t)t * H + c] = f4_to_h4(o);
}

// ---- K6: out = l2norm( [mean|g1] @ [Wl|Wr]^T + bl ), K=256 fp16 MMA ------------
__global__ void __launch_bounds__(256) k_sage_out(
    const float* __restrict__ Wl, const float* __restrict__ bl,
    const float* __restrict__ Wr, int n2, float* __restrict__ out) {
    extern __shared__ __half hsm[];
    __half* As = hsm;
    __half* Bs = hsm + 64 * HS2;
    float* psum = (float*)(hsm + 192 * HS2);
    float* scl  = psum + GROWS * 8;

    int row0 = blockIdx.x * GROWS;
    int tid = threadIdx.x, lane = tid & 31, warp = tid >> 5;
    int wm = warp >> 1, wn = warp & 1;
    int lq = lane >> 2, lr = lane & 3;

#pragma unroll
    for (int it = 0; it < 16; ++it) {
        int ch = it * 256 + tid;
        int r = ch >> 6, q = ch & 63;
        int row = row0 + r;
        uint2 v = make_uint2(0u, 0u);
        if (row < n2) {
            if (q < 32) v = *(const uint2*)&g_meanh[(size_t)row * H + q * 4];
            else        v = *(const uint2*)&g_g1h[(size_t)row * H + (q - 32) * 4];
        }
        int k = (q < 32) ? q * 4 : 128 + (q - 32) * 4;
        *(uint2*)&As[r * HS2 + k] = v;
    }
#pragma unroll
    for (int it = 0; it < 32; ++it) {
        int ch = it * 256 + tid;
        int j = ch >> 6, q = ch & 63;
        float4 v;
        int k;
        if (q < 32) { v = *(const float4*)&Wl[(size_t)j * H + q * 4]; k = q * 4; }
        else        { v = *(const float4*)&Wr[(size_t)j * H + (q - 32) * 4]; k = 128 + (q - 32) * 4; }
        *(uint2*)&Bs[j * HS2 + k] = f4_to_h4(v);
    }
    __syncthreads();

    float acc[8][4];
#pragma unroll
    for (int ni = 0; ni < 8; ++ni)
#pragma unroll
        for (int j = 0; j < 4; ++j) acc[ni][j] = 0.f;

#pragma unroll
    for (int ks = 0; ks < 16; ++ks) {
        int kb = ks * 16;
        int r0 = wm * 16 + lq;
        uint32_t a0 = *(const uint32_t*)&As[r0 * HS2 + kb + lr * 2];
        uint32_t a1 = *(const uint32_t*)&As[(r0 + 8) * HS2 + kb + lr * 2];
        uint32_t a2 = *(const uint32_t*)&As[r0 * HS2 + kb + 8 + lr * 2];
        uint32_t a3 = *(const uint32_t*)&As[(r0 + 8) * HS2 + kb + 8 + lr * 2];
#pragma unroll
        for (int ni = 0; ni < 8; ++ni) {
            int n = wn * 64 + ni * 8 + lq;
            uint32_t b0 = *(const uint32_t*)&Bs[n * HS2 + kb + lr * 2];
            uint32_t b1 = *(const uint32_t*)&Bs[n * HS2 + kb + 8 + lr * 2];
            MMA_F16(acc[ni], a0, a1, a2, a3, b0, b1);
        }
    }

    float p0 = 0.f, p8 = 0.f;
#pragma unroll
    for (int ni = 0; ni < 8; ++ni) {
        int col = wn * 64 + ni * 8 + lr * 2;
        float2 bb = *(const float2*)&bl[col];
        acc[ni][0] += bb.x; acc[ni][1] += bb.y;
        acc[ni][2] += bb.x; acc[ni][3] += bb.y;
        p0 += acc[ni][0] * acc[ni][0] + acc[ni][1] * acc[ni][1];
        p8 += acc[ni][2] * acc[ni][2] + acc[ni][3] * acc[ni][3];
    }
    int rl = wm * 16 + lq;
    psum[rl * 8 + wn * 4 + lr] = p0;
    psum[(rl + 8) * 8 + wn * 4 + lr] = p8;
    __syncthreads();
    if (tid < GROWS) {
        float ssum = 0.f;
#pragma unroll
        for (int c8 = 0; c8 < 8; ++c8) ssum += psum[tid * 8 + c8];
        scl[tid] = 1.f / fmaxf(sqrtf(ssum), 1e-12f);
    }
    __syncthreads();

    float s0 = scl[rl], s8 = scl[rl + 8];
    int row_a = row0 + rl, row_b = row0 + rl + 8;
#pragma unroll
    for (int ni = 0; ni < 8; ++ni) {
        int col = wn * 64 + ni * 8 + lr * 2;
        if (row_a < n2)
            *(float2*)&out[(size_t)row_a * H + col] =
                make_float2(acc[ni][0] * s0, acc[ni][1] * s0);
        if (row_b < n2)
            *(float2*)&out[(size_t)row_b * H + col] =
                make_float2(acc[ni][2] * s8, acc[ni][3] * s8);
    }
}

// ---------------------------------------------------------------------------
extern "C" void kernel_launch(void* const* d_in, const int* in_sizes, int n_in,
                              void* d_out, int out_size) {
    const float* x     = (const float*)d_in[0];
    const float* attr  = (const float*)d_in[1];
    const int*   e_id1 = (const int*)d_in[3];
    const int*   src1  = (const int*)d_in[6];
    const int*   tgt1  = (const int*)d_in[7];
    const int*   n1p   = (const int*)d_in[8];
    const float* gcn_W = (const float*)d_in[10];
    const float* gcn_b = (const float*)d_in[11];
    const float* Wl1   = (const float*)d_in[15];
    const float* bl1   = (const float*)d_in[16];
    const float* Wr1   = (const float*)d_in[17];
    float* out = (float*)d_out;

    int N0 = in_sizes[0] / H;  if (N0 > MAXN0) N0 = MAXN0;
    int E1 = in_sizes[3];      if (E1 > MAXE)  E1 = MAXE;
    int n2 = out_size / H;     if (n2 > MAXN2) n2 = MAXN2;

    constexpr int SMEM_GEMM = 2 * 128 * HSTR * 2;
    constexpr int SMEM_SOUT = 192 * HS2 * 2 + GROWS * 8 * 4 + GROWS * 4;
    cudaFuncSetAttribute(k_gemm_tc, cudaFuncAttributeMaxDynamicSharedMemorySize, SMEM_GEMM);
    cudaFuncSetAttribute(k_sage_out, cudaFuncAttributeMaxDynamicSharedMemorySize, SMEM_SOUT);

    cudaStream_t s2;
    cudaStreamCreateWithFlags(&s2, cudaStreamNonBlocking);
    cudaEvent_t evFork, evGemm;
    cudaEventCreateWithFlags(&evFork, cudaEventDisableTiming);
    cudaEventCreateWithFlags(&evGemm, cudaEventDisableTiming);

    cudaEventRecord(evFork, 0);
    cudaStreamWaitEvent(s2, evFork, 0);
    k_gemm_tc<<<(N0 + 127) / 128, 256, SMEM_GEMM, s2>>>(x, gcn_W, n1p, N0);
    cudaEventRecord(evGemm, s2);

    k_hist_scan<<<(E1 + 2047) / 2048, 1024>>>(attr, e_id1, tgt1, E1, n2);
    k_scatter<<<(E1 + 511) / 512, 256>>>(src1, tgt1, E1, n2);

    cudaStreamWaitEvent(0, evGemm, 0);

    k_gather_gcn<<<(n2 + 7) / 8, 256>>>(gcn_b, n2);
    k_sage2<<<(n2 + 7) / 8, 256>>>(gcn_b, n2);
    k_sage_out<<<(n2 + GROWS - 1) / GROWS, 256, SMEM_SOUT>>>(Wl1, bl1, Wr1, n2, out);
}

// round 17
// speedup vs baseline: 1.0704x; 1.0371x over previous
#include <cuda_runtime.h>
#include <cuda_fp16.h>
#include <cstdint>

// ---------------------------------------------------------------------------
// GlobalGNN layer-1-only pipeline (round-14 structure + PDL launches):
//   s2  : xW = x@gcn_W^T (fp16 MMA m16n8k16, fp32 accum, fp16 out)
//   main: hist(x2) -> scan -> scatter(x2)      [PDL-chained]
//   join: gather_gcn -> sage2 -> sage_out      [PDL-chained]
// Consumers call cudaGridDependencySynchronize() before touching producer data.
// ---------------------------------------------------------------------------

#define H 128
#define MAXN0 131072
#define MAXN2 16384
#define MAXE  1048576
#define GROWS 64
#define HSTR 136
#define HS2  264

__device__ __align__(16) __half g_xWh  [(size_t)MAXN0 * H];
__device__ __align__(16) __half g_aggh [(size_t)MAXN2 * H];
__device__ __align__(16) __half g_g1h  [(size_t)MAXN2 * H];
__device__ __align__(16) __half g_meanh[(size_t)MAXN2 * H];
__device__ __align__(16) __half g_p1h  [(size_t)MAXN2 * H];
__device__ __align__(16) int    g_hd   [2 * MAXN2];
__device__ __align__(16) int    g_off  [MAXN2 + 4];
__device__ __align__(16) float2 g_epk  [MAXE];
__device__ __align__(16) float  g_wst  [MAXE];

__device__ __forceinline__ int clamp_n1(const int* p, int N0) {
    int v = *p;
    if (v <= 0 || v > N0) v = N0;
    return v;
}

__device__ __forceinline__ float4 h4_to_f4(uint2 raw) {
    __half2 h0 = *reinterpret_cast<__half2*>(&raw.x);
    __half2 h1 = *reinterpret_cast<__half2*>(&raw.y);
    float2 f0 = __half22float2(h0);
    float2 f1 = __half22float2(h1);
    return make_float4(f0.x, f0.y, f1.x, f1.y);
}

__device__ __forceinline__ uint2 f4_to_h4(float4 v) {
    __half2 h0 = __floats2half2_rn(v.x, v.y);
    __half2 h1 = __floats2half2_rn(v.z, v.w);
    uint2 r;
    r.x = *reinterpret_cast<uint32_t*>(&h0);
    r.y = *reinterpret_cast<uint32_t*>(&h1);
    return r;
}

#define MMA_F16(d, a0, a1, a2, a3, b0, b1)                                    \
    asm volatile(                                                             \
        "mma.sync.aligned.m16n8k16.row.col.f32.f16.f16.f32 "                  \
        "{%0,%1,%2,%3},{%4,%5,%6,%7},{%8,%9},{%0,%1,%2,%3};"                  \
        : "+f"(d[0]), "+f"(d[1]), "+f"(d[2]), "+f"(d[3])                      \
        : "r"(a0), "r"(a1), "r"(a2), "r"(a3), "r"(b0), "r"(b1))

// ---- K1: histogram + weighted degree + weight staging, 2 edges/thread ---------
__global__ void k_hist(const float* __restrict__ attr, const int* __restrict__ eid,
                       const int* __restrict__ tgt, int E, int n2) {
    int base = (blockIdx.x * blockDim.x + threadIdx.x) * 2;
    if (base >= E) return;
    if (base + 2 <= E) {
        int2 t2  = *(const int2*)&tgt[base];
        int2 id2 = *(const int2*)&eid[base];
        float w0 = __ldg(&attr[id2.x]);
        float w1 = __ldg(&attr[id2.y]);
        *(float2*)&g_wst[base] = make_float2(w0, w1);
        if (t2.x < n2) { atomicAdd(&g_hd[t2.x], 1); atomicAdd((float*)&g_hd[MAXN2 + t2.x], w0); }
        if (t2.y < n2) { atomicAdd(&g_hd[t2.y], 1); atomicAdd((float*)&g_hd[MAXN2 + t2.y], w1); }
    } else {
        int t = __ldg(&tgt[base]);
        float w = __ldg(&attr[__ldg(&eid[base])]);
        g_wst[base] = w;
        if (t < n2) {
            atomicAdd(&g_hd[t], 1);
            atomicAdd((float*)&g_hd[MAXN2 + t], w);
        }
    }
}

// ---- K2: scan: g_off[i]=exclusive, g_hd[i]=inclusive end (i<n2) ----------------
__global__ void __launch_bounds__(1024) k_scan(int n2) {
    cudaGridDependencySynchronize();
    extern __shared__ int sh[];
    __shared__ int wsum[32];
    int tid = threadIdx.x, lane = tid & 31, wid = tid >> 5;

    int n2v = (n2 + 3) >> 2;
    const int4* cnt4 = (const int4*)g_hd;
    for (int v = tid; v < n2v; v += 1024)
        ((int4*)sh)[v] = cnt4[v];
    for (int v = n2v + tid; v < MAXN2 / 4; v += 1024)
        ((int4*)sh)[v] = make_int4(0, 0, 0, 0);
    __syncthreads();

    int base = tid * 16;
    int vals[16], cnts[16];
    int local = 0;
#pragma unroll
    for (int i4 = 0; i4 < 4; ++i4) {
        int4 q = *(const int4*)&sh[base + i4 * 4];
        int cc[4] = {q.x, q.y, q.z, q.w};
#pragma unroll
        for (int j = 0; j < 4; ++j) {
            vals[i4 * 4 + j] = local;
            cnts[i4 * 4 + j] = cc[j];
            local += cc[j];
        }
    }
    int inc = local;
#pragma unroll
    for (int off = 1; off < 32; off <<= 1) {
        int nb = __shfl_up_sync(0xffffffffu, inc, off);
        if (lane >= off) inc += nb;
    }
    if (lane == 31) wsum[wid] = inc;
    __syncthreads();
    if (wid == 0) {
        int s = wsum[lane];
#pragma unroll
        for (int off = 1; off < 32; off <<= 1) {
            int nb = __shfl_up_sync(0xffffffffu, s, off);
            if (lane >= off) s += nb;
        }
        wsum[lane] = s;
    }
    __syncthreads();
    int excl = ((wid > 0) ? wsum[wid - 1] : 0) + inc - local;
#pragma unroll
    for (int i4 = 0; i4 < 4; ++i4) {
        int idx = base + i4 * 4;
        int4 q = make_int4(excl + vals[i4 * 4],     excl + vals[i4 * 4 + 1],
                           excl + vals[i4 * 4 + 2], excl + vals[i4 * 4 + 3]);
        if (idx + 3 < n2) {
            *(int4*)&g_off[idx] = q;
            int4 e = make_int4(q.x + cnts[i4 * 4],     q.y + cnts[i4 * 4 + 1],
                               q.z + cnts[i4 * 4 + 2], q.w + cnts[i4 * 4 + 3]);
            *(int4*)&g_hd[idx] = e;
        } else {
#pragma unroll
            for (int j = 0; j < 4; ++j) {
                if (idx + j < n2) {
                    g_off[idx + j] = (&q.x)[j];
                    g_hd[idx + j] = (&q.x)[j] + cnts[i4 * 4 + j];
                }
            }
        }
    }
    if (tid == 0) g_off[n2] = wsum[31];
}

// ---- K3: scatter (countdown on end positions), 2 edges/thread ------------------
__global__ void k_scatter(const int* __restrict__ src, const int* __restrict__ tgt,
                          int E, int n2) {
    cudaGridDependencySynchronize();
    int base = (blockIdx.x * blockDim.x + threadIdx.x) * 2;
    if (base >= E) return;
    int t[2], s[2];
    float w[2];
    if (base + 2 <= E) {
        int2 t2 = *(const int2*)&tgt[base];
        int2 s2 = *(const int2*)&src[base];
        float2 w2 = *(const float2*)&g_wst[base];
        t[0] = t2.x; t[1] = t2.y;
        s[0] = s2.x; s[1] = s2.y;
        w[0] = w2.x; w[1] = w2.y;
    } else {
        t[0] = __ldg(&tgt[base]); t[1] = n2;
        s[0] = __ldg(&src[base]); s[1] = 0;
        w[0] = __ldg(&g_wst[base]); w[1] = 0.f;
    }
    int pos[2];
#pragma unroll
    for (int j = 0; j < 2; ++j)
        pos[j] = (t[j] < n2) ? (atomicAdd(&g_hd[t[j]], -1) - 1) : -1;
#pragma unroll
    for (int j = 0; j < 2; ++j)
        if (pos[j] >= 0)
            g_epk[pos[j]] = make_float2(__int_as_float(s[j]), w[j]);
}

// ---- K4: xW = x @ W^T via fp16 MMA (m16n8k16, fp32 accum), rows < n1 -----------
__global__ void __launch_bounds__(256) k_gemm_tc(
    const float* __restrict__ x, const float* __restrict__ W,
    const int* __restrict__ n1p, int N0) {
    extern __shared__ __half hsm[];
    __half* xs = hsm;
    __half* ws = hsm + 128 * HSTR;

    int n1 = clamp_n1(n1p, N0);
    int row0 = blockIdx.x * 128;
    if (row0 >= n1) return;

    int tid = threadIdx.x, lane = tid & 31, warp = tid >> 5;
    int wm = warp >> 1, wn = warp & 1;
    int lq = lane >> 2, lr = lane & 3;

#pragma unroll
    for (int it = 0; it < 16; ++it) {
        int f4 = it * 256 + tid;
        int r = f4 >> 5, k4 = f4 & 31;
        int row = row0 + r;
        float4 v = make_float4(0.f, 0.f, 0.f, 0.f);
        if (row < N0) v = *(const float4*)&x[(size_t)row * H + k4 * 4];
        *(uint2*)&xs[r * HSTR + k4 * 4] = f4_to_h4(v);
        float4 wv = *(const float4*)&W[(size_t)r * H + k4 * 4];
        *(uint2*)&ws[r * HSTR + k4 * 4] = f4_to_h4(wv);
    }
    __syncthreads();

    float acc[2][8][4];
#pragma unroll
    for (int mi = 0; mi < 2; ++mi)
#pragma unroll
        for (int ni = 0; ni < 8; ++ni)
#pragma unroll
            for (int j = 0; j < 4; ++j) acc[mi][ni][j] = 0.f;

#pragma unroll
    for (int ks = 0; ks < 8; ++ks) {
        int kb = ks * 16;
        uint32_t a[2][4];
#pragma unroll
        for (int mi = 0; mi < 2; ++mi) {
            int r0 = wm * 32 + mi * 16 + lq;
            a[mi][0] = *(const uint32_t*)&xs[r0 * HSTR + kb + lr * 2];
            a[mi][1] = *(const uint32_t*)&xs[(r0 + 8) * HSTR + kb + lr * 2];
            a[mi][2] = *(const uint32_t*)&xs[r0 * HSTR + kb + 8 + lr * 2];
            a[mi][3] = *(const uint32_t*)&xs[(r0 + 8) * HSTR + kb + 8 + lr * 2];
        }
#pragma unroll
        for (int ni = 0; ni < 8; ++ni) {
            int n = wn * 64 + ni * 8 + lq;
            uint32_t b0 = *(const uint32_t*)&ws[n * HSTR + kb + lr * 2];
            uint32_t b1 = *(const uint32_t*)&ws[n * HSTR + kb + 8 + lr * 2];
#pragma unroll
            for (int mi = 0; mi < 2; ++mi)
                MMA_F16(acc[mi][ni], a[mi][0], a[mi][1], a[mi][2], a[mi][3], b0, b1);
        }
    }

#pragma unroll
    for (int mi = 0; mi < 2; ++mi) {
        int r0 = row0 + wm * 32 + mi * 16 + lq;
#pragma unroll
        for (int ni = 0; ni < 8; ++ni) {
            int col = wn * 64 + ni * 8 + lr * 2;
            if (r0 < n1) {
                __half2 h = __floats2half2_rn(acc[mi][ni][0], acc[mi][ni][1]);
                *(__half2*)&g_xWh[(size_t)r0 * H + col] = h;
            }
            if (r0 + 8 < n1) {
                __half2 h = __floats2half2_rn(acc[mi][ni][2], acc[mi][ni][3]);
                *(__half2*)&g_xWh[(size_t)(r0 + 8) * H + col] = h;
            }
        }
    }
}

// ---- K5: GCN gather + SAGE partial p1 (t<n2), warp/target, unroll 8 ------------
__global__ void __launch_bounds__(256) k_gather_gcn(const float* __restrict__ b, int n2) {
    cudaGridDependencySynchronize();
    int t = blockIdx.x * 8 + (threadIdx.x >> 5);
    if (t >= n2) return;
    int lane = threadIdx.x & 31;
    int c = lane * 4;
    int base = __ldg(&g_off[t]);
    int end  = __ldg(&g_off[t + 1]);

    float4 ag0 = make_float4(0.f, 0.f, 0.f, 0.f), ag1 = ag0;
    float4 ap0 = ag0, ap1 = ag0;

    for (int i0 = base; i0 < end; i0 += 32) {
        int idx = i0 + lane;
        int s = 0;
        uint32_t pk = 0;
        if (idx < end) {
            float2 p = __ldg(&g_epk[idx]);
            s = __float_as_int(p.x);
            float w = p.y;
            float ds = 1.f, d2 = 1.f;
            if (s < n2) {
                float dg = __int_as_float(__ldg(&g_hd[MAXN2 + s]));
                d2 = 1.f / (1.f + dg);
                ds = rsqrtf(1.f + dg);
            }
            __half2 ph = __floats2half2_rn(ds * w, d2);
            pk = *reinterpret_cast<uint32_t*>(&ph);
        }
        int cnt = min(32, end - i0);
        int j = 0;
        for (; j + 8 <= cnt; j += 8) {
            int ss[8]; uint32_t pp[8];
#pragma unroll
            for (int q = 0; q < 8; ++q) {
                ss[q] = __shfl_sync(0xffffffffu, s, j + q);
                pp[q] = __shfl_sync(0xffffffffu, pk, j + q);
            }
            uint2 raw[8];
#pragma unroll
            for (int q = 0; q < 8; ++q)
                raw[q] = *(const uint2*)&g_xWh[(size_t)ss[q] * H + c];
#pragma unroll
            for (int q = 0; q < 8; ++q) {
                float2 wu = __half22float2(*reinterpret_cast<__half2*>(&pp[q]));
                float4 v = h4_to_f4(raw[q]);
                float4& ag = (q & 1) ? ag1 : ag0;
                float4& ap = (q & 1) ? ap1 : ap0;
                ag.x += wu.x * v.x; ag.y += wu.x * v.y; ag.z += wu.x * v.z; ag.w += wu.x * v.w;
                ap.x += wu.y * v.x; ap.y += wu.y * v.y; ap.z += wu.y * v.z; ap.w += wu.y * v.w;
            }
        }
        for (; j < cnt; ++j) {
            int s0 = __shfl_sync(0xffffffffu, s, j);
            uint32_t p0 = __shfl_sync(0xffffffffu, pk, j);
            float2 wu = __half22float2(*reinterpret_cast<__half2*>(&p0));
            float4 v = h4_to_f4(*(const uint2*)&g_xWh[(size_t)s0 * H + c]);
            ag0.x += wu.x * v.x; ag0.y += wu.x * v.y; ag0.z += wu.x * v.z; ag0.w += wu.x * v.w;
            ap0.x += wu.y * v.x; ap0.y += wu.y * v.y; ap0.z += wu.y * v.z; ap0.w += wu.y * v.w;
        }
    }

    float degt = __int_as_float(g_hd[MAXN2 + t]);
    float dt  = rsqrtf(1.f + degt);
    float d2t = 1.f / (1.f + degt);
    float4 agg;
    agg.x = (ag0.x + ag1.x) * dt;
    agg.y = (ag0.y + ag1.y) * dt;
    agg.z = (ag0.z + ag1.z) * dt;
    agg.w = (ag0.w + ag1.w) * dt;
    float4 p1 = make_float4(ap0.x + ap1.x, ap0.y + ap1.y, ap0.z + ap1.z, ap0.w + ap1.w);
    float4 xw = h4_to_f4(*(const uint2*)&g_xWh[(size_t)t * H + c]);
    float4 bb = *(const float4*)&b[c];
    float4 g1;
    g1.x = agg.x + xw.x * d2t + bb.x;
    g1.y = agg.y + xw.y * d2t + bb.y;
    g1.z = agg.z + xw.z * d2t + bb.z;
    g1.w = agg.w + xw.w * d2t + bb.w;
    *(uint2*)&g_g1h[(size_t)t * H + c] = f4_to_h4(g1);
    *(uint2*)&g_aggh[(size_t)t * H + c] = f4_to_h4(agg);
    *(uint2*)&g_p1h[(size_t)t * H + c] = f4_to_h4(p1);
}

// ---- K6: SAGE p2 gather + mean(fp16), unroll 8; restores g_hd[t] ---------------
__global__ void __launch_bounds__(256) k_sage2(const float* __restrict__ b, int n2) {
    cudaGridDependencySynchronize();
    int t = blockIdx.x * 8 + (threadIdx.x >> 5);
    if (t >= n2) return;
    int lane = threadIdx.x & 31;
    int c = lane * 4;
    int base = __ldg(&g_off[t]);
    int end  = __ldg(&g_off[t + 1]);
    int cnt = end - base;

    if (lane == 0) { g_hd[t] = 0; g_hd[MAXN2 + t] = 0; }

    float4 a0 = make_float4(0.f, 0.f, 0.f, 0.f), a1 = a0;

    for (int i0 = base; i0 < end; i0 += 32) {
        int idx = i0 + lane;
        int s = n2;
        if (idx < end) s = __float_as_int(__ldg(&g_epk[idx]).x);
        int cl = min(32, end - i0);
        int j = 0;
        for (; j + 8 <= cl; j += 8) {
            int ss[8];
#pragma unroll
            for (int q = 0; q < 8; ++q)
                ss[q] = __shfl_sync(0xffffffffu, s, j + q);
#pragma unroll
            for (int q = 0; q < 8; ++q) {
                if (ss[q] < n2) {
                    float4 v = h4_to_f4(*(const uint2*)&g_aggh[(size_t)ss[q] * H + c]);
                    float4& a = (q & 1) ? a1 : a0;
                    a.x += v.x; a.y += v.y; a.z += v.z; a.w += v.w;
                }
            }
        }
        for (; j < cl; ++j) {
            int s0 = __shfl_sync(0xffffffffu, s, j);
            if (s0 < n2) {
                float4 v = h4_to_f4(*(const uint2*)&g_aggh[(size_t)s0 * H + c]);
                a0.x += v.x; a0.y += v.y; a0.z += v.z; a0.w += v.w;
            }
        }
    }

    float4 o = make_float4(0.f, 0.f, 0.f, 0.f);
    if (cnt > 0) {
        float sc = 1.f / (float)cnt;
        float4 p1 = h4_to_f4(*(const uint2*)&g_p1h[(size_t)t * H + c]);
        float4 bb = *(const float4*)&b[c];
        o.x = (p1.x + a0.x + a1.x) * sc + bb.x;
        o.y = (p1.y + a0.y + a1.y) * sc + bb.y;
        o.z = (p1.z + a0.z + a1.z) * sc + bb.z;
        o.w = (p1.w + a0.w + a1.w) * sc + bb.w;
    }
    *(uint2*)&g_meanh[(size_t)t * H + c] = f4_to_h4(o);
}

// ---- K7: out = l2norm( [mean|g1] @ [Wl|Wr]^T + bl ), K=256 fp16 MMA ------------
__global__ void __launch_bounds__(256) k_sage_out(
    const float* __restrict__ Wl, const float* __restrict__ bl,
    const float* __restrict__ Wr, int n2, float* __restrict__ out) {
    extern __shared__ __half hsm[];
    __half* As = hsm;
    __half* Bs = hsm + 64 * HS2;
    float* psum = (float*)(hsm + 192 * HS2);
    float* scl  = psum + GROWS * 8;

    int row0 = blockIdx.x * GROWS;
    int tid = threadIdx.x, lane = tid & 31, warp = tid >> 5;
    int wm = warp >> 1, wn = warp & 1;
    int lq = lane >> 2, lr = lane & 3;

    // B load (input weights — independent of predecessor) can proceed before sync
#pragma unroll
    for (int it = 0; it < 32; ++it) {
        int ch = it * 256 + tid;
        int j = ch >> 6, q = ch & 63;
        float4 v;
        int k;
        if (q < 32) { v = *(const float4*)&Wl[(size_t)j * H + q * 4]; k = q * 4; }
        else        { v = *(const float4*)&Wr[(size_t)j * H + (q - 32) * 4]; k = 128 + (q - 32) * 4; }
        *(uint2*)&Bs[j * HS2 + k] = f4_to_h4(v);
    }

    cudaGridDependencySynchronize();

#pragma unroll
    for (int it = 0; it < 16; ++it) {
        int ch = it * 256 + tid;
        int r = ch >> 6, q = ch & 63;
        int row = row0 + r;
        uint2 v = make_uint2(0u, 0u);
        if (row < n2) {
            if (q < 32) v = *(const uint2*)&g_meanh[(size_t)row * H + q * 4];
            else        v = *(const uint2*)&g_g1h[(size_t)row * H + (q - 32) * 4];
        }
        int k = (q < 32) ? q * 4 : 128 + (q - 32) * 4;
        *(uint2*)&As[r * HS2 + k] = v;
    }
    __syncthreads();

    float acc[8][4];
#pragma unroll
    for (int ni = 0; ni < 8; ++ni)
#pragma unroll
        for (int j = 0; j < 4; ++j) acc[ni][j] = 0.f;

#pragma unroll
    for (int ks = 0; ks < 16; ++ks) {
        int kb = ks * 16;
        int r0 = wm * 16 + lq;
        uint32_t a0 = *(const uint32_t*)&As[r0 * HS2 + kb + lr * 2];
        uint32_t a1 = *(const uint32_t*)&As[(r0 + 8) * HS2 + kb + lr * 2];
        uint32_t a2 = *(const uint32_t*)&As[r0 * HS2 + kb + 8 + lr * 2];
        uint32_t a3 = *(const uint32_t*)&As[(r0 + 8) * HS2 + kb + 8 + lr * 2];
#pragma unroll
        for (int ni = 0; ni < 8; ++ni) {
            int n = wn * 64 + ni * 8 + lq;
            uint32_t b0 = *(const uint32_t*)&Bs[n * HS2 + kb + lr * 2];
            uint32_t b1 = *(const uint32_t*)&Bs[n * HS2 + kb + 8 + lr * 2];
            MMA_F16(acc[ni], a0, a1, a2, a3, b0, b1);
        }
    }

    float p0 = 0.f, p8 = 0.f;
#pragma unroll
    for (int ni = 0; ni < 8; ++ni) {
        int col = wn * 64 + ni * 8 + lr * 2;
        float2 bb = *(const float2*)&bl[col];
        acc[ni][0] += bb.x; acc[ni][1] += bb.y;
        acc[ni][2] += bb.x; acc[ni][3] += bb.y;
        p0 += acc[ni][0] * acc[ni][0] + acc[ni][1] * acc[ni][1];
        p8 += acc[ni][2] * acc[ni][2] + acc[ni][3] * acc[ni][3];
    }
    int rl = wm * 16 + lq;
    psum[rl * 8 + wn * 4 + lr] = p0;
    psum[(rl + 8) * 8 + wn * 4 + lr] = p8;
    __syncthreads();
    if (tid < GROWS) {
        float ssum = 0.f;
#pragma unroll
        for (int c8 = 0; c8 < 8; ++c8) ssum += psum[tid * 8 + c8];
        scl[tid] = 1.f / fmaxf(sqrtf(ssum), 1e-12f);
    }
    __syncthreads();

    float s0 = scl[rl], s8 = scl[rl + 8];
    int row_a = row0 + rl, row_b = row0 + rl + 8;
#pragma unroll
    for (int ni = 0; ni < 8; ++ni) {
        int col = wn * 64 + ni * 8 + lr * 2;
        if (row_a < n2)
            *(float2*)&out[(size_t)row_a * H + col] =
                make_float2(acc[ni][0] * s0, acc[ni][1] * s0);
        if (row_b < n2)
            *(float2*)&out[(size_t)row_b * H + col] =
                make_float2(acc[ni][2] * s8, acc[ni][3] * s8);
    }
}

// ---------------------------------------------------------------------------
extern "C" void kernel_launch(void* const* d_in, const int* in_sizes, int n_in,
                              void* d_out, int out_size) {
    const float* x     = (const float*)d_in[0];
    const float* attr  = (const float*)d_in[1];
    const int*   e_id1 = (const int*)d_in[3];
    const int*   src1  = (const int*)d_in[6];
    const int*   tgt1  = (const int*)d_in[7];
    const int*   n1p   = (const int*)d_in[8];
    const float* gcn_W = (const float*)d_in[10];
    const float* gcn_b = (const float*)d_in[11];
    const float* Wl1   = (const float*)d_in[15];
    const float* bl1   = (const float*)d_in[16];
    const float* Wr1   = (const float*)d_in[17];
    float* out = (float*)d_out;

    int N0 = in_sizes[0] / H;  if (N0 > MAXN0) N0 = MAXN0;
    int E1 = in_sizes[3];      if (E1 > MAXE)  E1 = MAXE;
    int n2 = out_size / H;     if (n2 > MAXN2) n2 = MAXN2;

    constexpr int SMEM_GEMM = 2 * 128 * HSTR * 2;
    constexpr int SMEM_SCAN = MAXN2 * 4;
    constexpr int SMEM_SOUT = 192 * HS2 * 2 + GROWS * 8 * 4 + GROWS * 4;
    cudaFuncSetAttribute(k_gemm_tc, cudaFuncAttributeMaxDynamicSharedMemorySize, SMEM_GEMM);
    cudaFuncSetAttribute(k_scan, cudaFuncAttributeMaxDynamicSharedMemorySize, SMEM_SCAN);
    cudaFuncSetAttribute(k_sage_out, cudaFuncAttributeMaxDynamicSharedMemorySize, SMEM_SOUT);

    cudaStream_t s2;
    cudaStreamCreateWithFlags(&s2, cudaStreamNonBlocking);
    cudaEvent_t evFork, evGemm;
    cudaEventCreateWithFlags(&evFork, cudaEventDisableTiming);
    cudaEventCreateWithFlags(&evGemm, cudaEventDisableTiming);

    cudaLaunchAttribute pdl[1];
    pdl[0].id = cudaLaunchAttributeProgrammaticStreamSerialization;
    pdl[0].val.programmaticStreamSerializationAllowed = 1;

    // Fork: GEMM on side stream (normal launch).
    cudaEventRecord(evFork, 0);
    cudaStreamWaitEvent(s2, evFork, 0);
    k_gemm_tc<<<(N0 + 127) / 128, 256, SMEM_GEMM, s2>>>(x, gcn_W, n1p, N0);
    cudaEventRecord(evGemm, s2);

    // Main stream: hist (normal) -> scan (PDL) -> scatter (PDL)
    k_hist<<<(E1 + 511) / 512, 256>>>(attr, e_id1, tgt1, E1, n2);
    {
        cudaLaunchConfig_t c = {};
        c.gridDim = dim3(1); c.blockDim = dim3(1024);
        c.dynamicSmemBytes = SMEM_SCAN; c.stream = 0;
        c.attrs = pdl; c.numAttrs = 1;
        cudaLaunchKernelEx(&c, k_scan, n2);
    }
    {
        cudaLaunchConfig_t c = {};
        c.gridDim = dim3((E1 + 511) / 512); c.blockDim = dim3(256);
        c.stream = 0; c.attrs = pdl; c.numAttrs = 1;
        cudaLaunchKernelEx(&c, k_scatter, src1, tgt1, E1, n2);
    }

    cudaStreamWaitEvent(0, evGemm, 0);  // join

    {
        cudaLaunchConfig_t c = {};
        c.gridDim = dim3((n2 + 7) / 8); c.blockDim = dim3(256);
        c.stream = 0; c.attrs = pdl; c.numAttrs = 1;
        cudaLaunchKernelEx(&c, k_gather_gcn, (const float*)gcn_b, n2);
    }
    {
        cudaLaunchConfig_t c = {};
        c.gridDim = dim3((n2 + 7) / 8); c.blockDim = dim3(256);
        c.stream = 0; c.attrs = pdl; c.numAttrs = 1;
        cudaLaunchKernelEx(&c, k_sage2, (const float*)gcn_b, n2);
    }
    {
        cudaLaunchConfig_t c = {};
        c.gridDim = dim3((n2 + GROWS - 1) / GROWS); c.blockDim = dim3(256);
        c.dynamicSmemBytes = SMEM_SOUT; c.stream = 0;
        c.attrs = pdl; c.numAttrs = 1;
        cudaLaunchKernelEx(&c, k_sage_out, Wl1, bl1, Wr1, n2, (float*)out);
    }
}